// round 4
// baseline (speedup 1.0000x reference)
#include <cuda_runtime.h>
#include <cuda_bf16.h>
#include <math.h>

// Fixed problem shape (setup_inputs): B=8, H=W=96, D=768, 25 shifts, T=0.07
#define BB 8
#define HH 96
#define WW 96
#define DD 768
#define NN (HH*WW)
#define NC (DD/8)          // 96 chunks of 8 floats along D
#define TH 16              // tile rows per block
#define TW 32              // tile cols per block
#define HR (TH+4)          // halo rows = 20
#define HC (TW+4)          // halo cols = 36
#define RS 38              // padded smem row stride (floats)
#define PS (HR*RS)         // plane stride = 760 floats
#define HGAP 16            // offset for upper 4 planes (bank decorrelation)
#define BUFSZ (8*PS+HGAP)  // 6096 floats per buffer
#define NSTG 6             // ceil(2*HR*HC / 256) staging float4 slots per thread
#define NBLK (3*6*BB)      // 144 blocks

__device__ float g_wsum[2*BB];
__device__ float g_part[2][NBLK];

// ---------------------------------------------------------------------------
// Kernel 0: per-batch weight sums (deterministic fixed-order reduction)
// ---------------------------------------------------------------------------
__global__ void wsum_kernel(const float* __restrict__ w1,
                            const float* __restrict__ w2) {
    int b = blockIdx.x, tid = threadIdx.x;
    const float* p1 = w1 + b * NN;
    const float* p2 = w2 + b * NN;
    float s1 = 0.f, s2 = 0.f;
    for (int i = tid; i < NN; i += 256) { s1 += p1[i]; s2 += p2[i]; }
#pragma unroll
    for (int o = 16; o > 0; o >>= 1) {
        s1 += __shfl_down_sync(0xffffffffu, s1, o);
        s2 += __shfl_down_sync(0xffffffffu, s2, o);
    }
    __shared__ float sh[16];
    if ((tid & 31) == 0) { sh[tid >> 5] = s1; sh[8 + (tid >> 5)] = s2; }
    __syncthreads();
    if (tid == 0) {
        float t1 = 0.f, t2 = 0.f;
#pragma unroll
        for (int i = 0; i < 8; i++) { t1 += sh[i]; t2 += sh[8 + i]; }
        g_wsum[b] = t1; g_wsum[BB + b] = t2;
    }
}

// ---------------------------------------------------------------------------
// Main fused kernel: normalize + 25-shift dots + softmax + weighted reduce
// ---------------------------------------------------------------------------
__device__ __forceinline__ float f4c(const float4 v, int i) {
    return i == 0 ? v.x : i == 1 ? v.y : i == 2 ? v.z : v.w;
}

__global__ void __launch_bounds__(256, 1)
align_kernel(const float* __restrict__ z1, const float* __restrict__ z2,
             const float* __restrict__ w1, const float* __restrict__ w2) {
    __shared__ float smem[2 * BUFSZ + 32];

    const int tid = threadIdx.x;
    const int b   = blockIdx.z;
    const int th0 = blockIdx.y * TH, tw0 = blockIdx.x * TW;
    const int tr  = tid >> 4;        // 0..15 tile row
    const int tc  = tid & 15;        // 0..15
    const int wl  = tc * 2;          // first of 2 tokens

    // Staging map: float4 slot q = tid + k*256 -> halo token t = q>>1, half = q&1
    int goff[NSTG], soff[NSTG];
#pragma unroll
    for (int k = 0; k < NSTG; k++) {
        int q = tid + (k << 8);
        if (q < 2 * HR * HC) {
            int t = q >> 1, half = q & 1;
            int r = t / HC, cl = t - r * HC;
            int gh = th0 + r - 2, gw = tw0 + cl - 2;
            bool inb = ((unsigned)gh < HH) && ((unsigned)gw < WW);
            goff[k] = inb ? ((b * NN + gh * WW + gw) * DD + half * 4) : -1;
            soff[k] = half * (4 * PS + HGAP) + r * RS + cl;
        } else { goff[k] = -1; soff[k] = -1; }
    }

    const float* z1p =
        z1 + (size_t)(b * NN + (th0 + tr) * WW + (tw0 + wl)) * DD;

    // prefetch chunk 0 (z2 halo + z1 pair)
    float4 zbuf[NSTG];
#pragma unroll
    for (int k = 0; k < NSTG; k++)
        zbuf[k] = (goff[k] >= 0) ? *(const float4*)(z2 + goff[k])
                                 : make_float4(0.f, 0.f, 0.f, 0.f);
    float4 z1c[4];
    z1c[0] = *(const float4*)(z1p);
    z1c[1] = *(const float4*)(z1p + 4);
    z1c[2] = *(const float4*)(z1p + DD);
    z1c[3] = *(const float4*)(z1p + DD + 4);

    float sims[50];
#pragma unroll
    for (int s = 0; s < 50; s++) sims[s] = 0.f;
    float ss1_0 = 0.f, ss1_1 = 0.f;
    float ss2h[NSTG];
#pragma unroll
    for (int k = 0; k < NSTG; k++) ss2h[k] = 0.f;

    // store chunk 0 into buffer 0 (+ z2 sq-norm partials from registers)
#pragma unroll
    for (int k = 0; k < NSTG; k++)
        if (soff[k] >= 0) {
            float4 v = zbuf[k];
            float* d0 = smem + soff[k];
            d0[0] = v.x; d0[PS] = v.y; d0[2 * PS] = v.z; d0[3 * PS] = v.w;
            ss2h[k] += v.x * v.x + v.y * v.y + v.z * v.z + v.w * v.w;
        }
    __syncthreads();

#pragma unroll 1
    for (int c = 0; c < NC; c++) {
        const float* base = smem + (c & 1) * BUFSZ + tr * RS + wl;
        const bool more = (c + 1 < NC);

        // issue z2 prefetch for next chunk (consumed by store at loop bottom)
        if (more) {
#pragma unroll
            for (int k = 0; k < NSTG; k++)
                zbuf[k] = (goff[k] >= 0)
                    ? *(const float4*)(z2 + goff[k] + (size_t)(c + 1) * 8)
                    : make_float4(0.f, 0.f, 0.f, 0.f);
        }

        // d = 0..3 (z1c[0], z1c[2])
#pragma unroll
        for (int d = 0; d < 4; d++) {
            float a0 = f4c(z1c[0], d), a1 = f4c(z1c[2], d);
            ss1_0 += a0 * a0; ss1_1 += a1 * a1;
            const float* pd = base + d * PS;
#pragma unroll
            for (int dy = 0; dy < 5; dy++) {
                const float* row = pd + dy * RS;
                float2 q0 = *(const float2*)(row);
                float2 q1 = *(const float2*)(row + 2);
                float2 q2 = *(const float2*)(row + 4);
                int s = dy * 5;
                sims[s    ] += a0 * q0.x; sims[s + 1] += a0 * q0.y;
                sims[s + 2] += a0 * q1.x; sims[s + 3] += a0 * q1.y;
                sims[s + 4] += a0 * q2.x;
                sims[25 + s] += a1 * q0.y; sims[26 + s] += a1 * q1.x;
                sims[27 + s] += a1 * q1.y; sims[28 + s] += a1 * q2.x;
                sims[29 + s] += a1 * q2.y;
            }
        }
        if (more) {  // refill first z1 halves (now dead) for chunk c+1
            z1c[0] = *(const float4*)(z1p + (size_t)(c + 1) * 8);
            z1c[2] = *(const float4*)(z1p + DD + (size_t)(c + 1) * 8);
        }
        // d = 4..7 (z1c[1], z1c[3]); upper planes offset by HGAP
#pragma unroll
        for (int d = 0; d < 4; d++) {
            float a0 = f4c(z1c[1], d), a1 = f4c(z1c[3], d);
            ss1_0 += a0 * a0; ss1_1 += a1 * a1;
            const float* pd = base + HGAP + (d + 4) * PS;
#pragma unroll
            for (int dy = 0; dy < 5; dy++) {
                const float* row = pd + dy * RS;
                float2 q0 = *(const float2*)(row);
                float2 q1 = *(const float2*)(row + 2);
                float2 q2 = *(const float2*)(row + 4);
                int s = dy * 5;
                sims[s    ] += a0 * q0.x; sims[s + 1] += a0 * q0.y;
                sims[s + 2] += a0 * q1.x; sims[s + 3] += a0 * q1.y;
                sims[s + 4] += a0 * q2.x;
                sims[25 + s] += a1 * q0.y; sims[26 + s] += a1 * q1.x;
                sims[27 + s] += a1 * q1.y; sims[28 + s] += a1 * q2.x;
                sims[29 + s] += a1 * q2.y;
            }
        }
        if (more) {
            z1c[1] = *(const float4*)(z1p + (size_t)(c + 1) * 8 + 4);
            z1c[3] = *(const float4*)(z1p + DD + (size_t)(c + 1) * 8 + 4);
        }
        // store chunk c+1 into the other buffer (+ ss2 partials)
        if (more) {
            float* nb = smem + ((c + 1) & 1) * BUFSZ;
#pragma unroll
            for (int k = 0; k < NSTG; k++)
                if (soff[k] >= 0) {
                    float4 v = zbuf[k];
                    float* d0 = nb + soff[k];
                    d0[0] = v.x; d0[PS] = v.y; d0[2 * PS] = v.z; d0[3 * PS] = v.w;
                    ss2h[k] += v.x * v.x + v.y * v.y + v.z * v.z + v.w * v.w;
                }
        }
        __syncthreads();
    }

    // ---- epilogue: z2 halo inverse norms via smem exchange ---------------
    float* sA = smem;                        // 1440 half-norms
#pragma unroll
    for (int k = 0; k < NSTG; k++) {
        int q = tid + (k << 8);
        if (q < 2 * HR * HC) sA[q] = ss2h[k];
    }
    __syncthreads();
    float* sInv = smem + 1536;               // 720 inverse norms (disjoint region)
#pragma unroll
    for (int j = 0; j < 3; j++) {
        int t = tid + (j << 8);
        if (t < HR * HC) {
            float n2 = sA[2 * t] + sA[2 * t + 1];
            sInv[t] = 1.f / fmaxf(sqrtf(n2), 1e-12f);
        }
    }
    __syncthreads();

    const float inv1_0 = 1.f / fmaxf(sqrtf(ss1_0), 1e-12f);
    const float inv1_1 = 1.f / fmaxf(sqrtf(ss1_1), 1e-12f);
    const float invT   = 1.f / 0.07f;        // SHIFT_TEMP + 1e-10 == 0.07f in fp32
    const float iws1   = 1.f / (g_wsum[b] + 1e-10f);
    const float iws2   = 1.f / (g_wsum[BB + b] + 1e-10f);

    float partA = 0.f, partP = 0.f;
#pragma unroll
    for (int j = 0; j < 2; j++) {
        float inv1 = j ? inv1_1 : inv1_0;
        float sn[25];
        float m = -1e30f;
#pragma unroll
        for (int dy = 0; dy < 5; dy++)
#pragma unroll
            for (int dx = 0; dx < 5; dx++) {
                int t = (tr + dy) * HC + (wl + j + dx);
                float v = sims[j * 25 + dy * 5 + dx] * inv1 * sInv[t];
                sn[dy * 5 + dx] = v;
                m = fmaxf(m, v);
            }
        float se = 0.f, sv = 0.f;
#pragma unroll
        for (int s = 0; s < 25; s++) {
            float e = __expf((sn[s] - m) * invT);
            se += e; sv += e * sn[s];
        }
        float sb = sv / se;   // softmax-weighted best similarity
        int tok = (th0 + tr) * WW + tw0 + wl + j;
        float wa = 0.5f * (w1[b * NN + tok] * iws1 + w2[b * NN + tok] * iws2);
        partA += (1.f - sb) * wa;
        partP += sb;
    }

    // ---- deterministic block reduction (no atomics) ----------------------
#pragma unroll
    for (int o = 16; o > 0; o >>= 1) {
        partA += __shfl_down_sync(0xffffffffu, partA, o);
        partP += __shfl_down_sync(0xffffffffu, partP, o);
    }
    float* red = smem + 2 * BUFSZ;
    if ((tid & 31) == 0) { red[tid >> 5] = partA; red[8 + (tid >> 5)] = partP; }
    __syncthreads();
    if (tid == 0) {
        float a = 0.f, p = 0.f;
#pragma unroll
        for (int i = 0; i < 8; i++) { a += red[i]; p += red[8 + i]; }
        int bid = blockIdx.x + 3 * blockIdx.y + 18 * blockIdx.z;
        g_part[0][bid] = a;
        g_part[1][bid] = p;
    }
}

// ---------------------------------------------------------------------------
// Finalize: deterministic fixed-order sum of 144 block partials
// ---------------------------------------------------------------------------
__global__ void finalize_kernel(float* __restrict__ out) {
    int tid = threadIdx.x;
    float a = (tid < NBLK) ? g_part[0][tid] : 0.f;
    float p = (tid < NBLK) ? g_part[1][tid] : 0.f;
#pragma unroll
    for (int o = 16; o > 0; o >>= 1) {
        a += __shfl_down_sync(0xffffffffu, a, o);
        p += __shfl_down_sync(0xffffffffu, p, o);
    }
    __shared__ float sh[16];
    if ((tid & 31) == 0) { sh[tid >> 5] = a; sh[8 + (tid >> 5)] = p; }
    __syncthreads();
    if (tid == 0) {
        float ta = 0.f, tp = 0.f;
#pragma unroll
        for (int i = 0; i < 8; i++) { ta += sh[i]; tp += sh[8 + i]; }
        out[0] = ta / (float)BB;             // align_loss (mean over batch)
        out[1] = tp / (float)(BB * NN);      // pos_similarity (mean over tokens)
    }
}

// ---------------------------------------------------------------------------
extern "C" void kernel_launch(void* const* d_in, const int* in_sizes, int n_in,
                              void* d_out, int out_size) {
    const float* z1 = (const float*)d_in[0];
    const float* z2 = (const float*)d_in[1];
    const float* w1 = (const float*)d_in[2];
    const float* w2 = (const float*)d_in[3];
    float* out = (float*)d_out;

    wsum_kernel<<<BB, 256>>>(w1, w2);
    dim3 grid(WW / TW, HH / TH, BB);         // (3, 6, 8) = 144 blocks
    align_kernel<<<grid, 256>>>(z1, z2, w1, w2);
    finalize_kernel<<<1, 256>>>(out);
}

// round 5
// speedup vs baseline: 1.1946x; 1.1946x over previous
#include <cuda_runtime.h>
#include <cuda_bf16.h>
#include <math.h>

// Fixed shape (setup_inputs): B=8, H=W=96, D=768, 25 shifts, temp 0.07
#define BB 8
#define HH 96
#define WW 96
#define DD 768
#define NN (HH*WW)
#define TH 16              // tile rows
#define TW 32              // tile cols
#define HR (TH+4)          // halo rows = 20
#define HC (TW+4)          // halo cols = 36
#define RS 38              // padded smem row stride
#define PS (HR*RS)         // plane stride = 760
#define HGAP 16            // bank decorrelation for planes 4..7
#define BUFSZ (8*PS+HGAP)  // 6096 floats
#define NSTG 6             // staging float4 slots per thread (per group)
#define NITER 48           // chunks per D-half (8 floats each)
#define NBLK (3*6*BB)      // 144 blocks
// scratch layout inside the 4-buffer smem region (reused post-loop)
#define SCR_MERGE 0            // 256*53 = 13568 floats
#define SCR_SA    13568        // 2*1440 = 2880 floats
#define SCR_SINV  16448        // 720 floats
#define SCR_RED   17200        // 5*16 floats
#define SMEM_FLT  (4*BUFSZ)    // 24384 floats = 97536 B

__device__ float g_part[5][NBLK];   // a1, a2, p, s1, s2 per block

__device__ __forceinline__ float f4c(const float4 v, int i) {
    return i == 0 ? v.x : i == 1 ? v.y : i == 2 ? v.z : v.w;
}

extern __shared__ float smem[];

__global__ void __launch_bounds__(512, 1)
align_kernel(const float* __restrict__ z1, const float* __restrict__ z2,
             const float* __restrict__ w1, const float* __restrict__ w2) {
    const int tid = threadIdx.x;
    const int g   = tid >> 8;        // D-split group: 0 -> d[0,384), 1 -> d[384,768)
    const int gt  = tid & 255;
    const int b   = blockIdx.z;
    const int th0 = blockIdx.y * TH, tw0 = blockIdx.x * TW;
    const int tr  = gt >> 4;         // 0..15 tile row
    const int tc  = gt & 15;
    const int wl  = tc * 2;          // first of 2 tokens

    float* bufA = smem + (g * 2    ) * BUFSZ;
    float* bufB = smem + (g * 2 + 1) * BUFSZ;

    // staging map: float4 slot q = gt + 256k  ->  halo token t = q>>1, half = q&1
    int goff[NSTG], soff[NSTG];
#pragma unroll
    for (int k = 0; k < NSTG; k++) {
        int q = gt + (k << 8);
        if (q < 2 * HR * HC) {
            int t = q >> 1, half = q & 1;
            int r = t / HC, cl = t - r * HC;
            int gh = th0 + r - 2, gw = tw0 + cl - 2;
            bool inb = ((unsigned)gh < HH) && ((unsigned)gw < WW);
            goff[k] = inb ? ((b * NN + gh * WW + gw) * DD + g * 384 + half * 4) : -1;
            soff[k] = half * (4 * PS + HGAP) + r * RS + cl;
        } else { goff[k] = -1; soff[k] = -1; }
    }

    const float* z1p =
        z1 + (size_t)(b * NN + (th0 + tr) * WW + (tw0 + wl)) * DD + g * 384;

    float sims[50];
#pragma unroll
    for (int s = 0; s < 50; s++) sims[s] = 0.f;
    float ss1_0 = 0.f, ss1_1 = 0.f;
    float ss2h[NSTG];
#pragma unroll
    for (int k = 0; k < NSTG; k++) ss2h[k] = 0.f;

    // prologue: stage chunk 0 into bufA (immediate LDG->STS) + z1 chunk 0
#pragma unroll
    for (int k = 0; k < NSTG; k++)
        if (soff[k] >= 0) {
            float4 v = (goff[k] >= 0) ? *(const float4*)(z2 + goff[k])
                                      : make_float4(0.f, 0.f, 0.f, 0.f);
            float* d0 = bufA + soff[k];
            d0[0] = v.x; d0[PS] = v.y; d0[2 * PS] = v.z; d0[3 * PS] = v.w;
            ss2h[k] += v.x * v.x + v.y * v.y + v.z * v.z + v.w * v.w;
        }
    float4 z1c[4];
    z1c[0] = *(const float4*)(z1p);
    z1c[1] = *(const float4*)(z1p + 4);
    z1c[2] = *(const float4*)(z1p + DD);
    z1c[3] = *(const float4*)(z1p + DD + 4);
    __syncthreads();

#pragma unroll 1
    for (int c = 0; c < NITER; c++) {
        const float* base = ((c & 1) ? bufB : bufA) + tr * RS + wl;
        float* nxt = (c & 1) ? bufA : bufB;
        const bool more = (c + 1 < NITER);

        // stage chunk c+1 into the other buffer (immediate, latency hidden)
        if (more) {
#pragma unroll
            for (int k = 0; k < NSTG; k++)
                if (soff[k] >= 0) {
                    float4 v = (goff[k] >= 0)
                        ? *(const float4*)(z2 + goff[k] + (size_t)(c + 1) * 8)
                        : make_float4(0.f, 0.f, 0.f, 0.f);
                    float* d0 = nxt + soff[k];
                    d0[0] = v.x; d0[PS] = v.y; d0[2 * PS] = v.z; d0[3 * PS] = v.w;
                    ss2h[k] += v.x * v.x + v.y * v.y + v.z * v.z + v.w * v.w;
                }
        }

        // d = 0..3 (z1c[0], z1c[2]), planes 0..3
#pragma unroll
        for (int d = 0; d < 4; d++) {
            float a0 = f4c(z1c[0], d), a1 = f4c(z1c[2], d);
            ss1_0 += a0 * a0; ss1_1 += a1 * a1;
            const float* pd = base + d * PS;
#pragma unroll
            for (int dy = 0; dy < 5; dy++) {
                const float* row = pd + dy * RS;
                float2 q0 = *(const float2*)(row);
                float2 q1 = *(const float2*)(row + 2);
                float2 q2 = *(const float2*)(row + 4);
                int s = dy * 5;
                sims[s    ] += a0 * q0.x; sims[s + 1] += a0 * q0.y;
                sims[s + 2] += a0 * q1.x; sims[s + 3] += a0 * q1.y;
                sims[s + 4] += a0 * q2.x;
                sims[25 + s] += a1 * q0.y; sims[26 + s] += a1 * q1.x;
                sims[27 + s] += a1 * q1.y; sims[28 + s] += a1 * q2.x;
                sims[29 + s] += a1 * q2.y;
            }
        }
        if (more) {
            z1c[0] = *(const float4*)(z1p + (size_t)(c + 1) * 8);
            z1c[2] = *(const float4*)(z1p + DD + (size_t)(c + 1) * 8);
        }
        // d = 4..7 (z1c[1], z1c[3]), planes 4..7 (+HGAP)
#pragma unroll
        for (int d = 0; d < 4; d++) {
            float a0 = f4c(z1c[1], d), a1 = f4c(z1c[3], d);
            ss1_0 += a0 * a0; ss1_1 += a1 * a1;
            const float* pd = base + HGAP + (d + 4) * PS;
#pragma unroll
            for (int dy = 0; dy < 5; dy++) {
                const float* row = pd + dy * RS;
                float2 q0 = *(const float2*)(row);
                float2 q1 = *(const float2*)(row + 2);
                float2 q2 = *(const float2*)(row + 4);
                int s = dy * 5;
                sims[s    ] += a0 * q0.x; sims[s + 1] += a0 * q0.y;
                sims[s + 2] += a0 * q1.x; sims[s + 3] += a0 * q1.y;
                sims[s + 4] += a0 * q2.x;
                sims[25 + s] += a1 * q0.y; sims[26 + s] += a1 * q1.x;
                sims[27 + s] += a1 * q1.y; sims[28 + s] += a1 * q2.x;
                sims[29 + s] += a1 * q2.y;
            }
        }
        if (more) {
            z1c[1] = *(const float4*)(z1p + (size_t)(c + 1) * 8 + 4);
            z1c[3] = *(const float4*)(z1p + DD + (size_t)(c + 1) * 8 + 4);
        }
        __syncthreads();
    }

    // ---- exchange: z2 norm partials + group-1 sims -> scratch -------------
#pragma unroll
    for (int k = 0; k < NSTG; k++) {
        int q = gt + (k << 8);
        if (q < 2 * HR * HC) smem[SCR_SA + g * 1440 + q] = ss2h[k];
    }
    if (g == 1) {
        float* s = smem + SCR_MERGE + gt * 53;
#pragma unroll
        for (int i = 0; i < 50; i++) s[i] = sims[i];
        s[50] = ss1_0; s[51] = ss1_1;
    }
    __syncthreads();

    // z2 halo inverse norms (combine 2 halves x 2 groups)
    for (int t = tid; t < HR * HC; t += 512) {
        float n2 = smem[SCR_SA + 2 * t] + smem[SCR_SA + 2 * t + 1]
                 + smem[SCR_SA + 1440 + 2 * t] + smem[SCR_SA + 1440 + 2 * t + 1];
        smem[SCR_SINV + t] = 1.f / fmaxf(sqrtf(n2), 1e-12f);
    }
    // group 0 merges group 1's sims/ss1
    if (g == 0) {
        const float* s = smem + SCR_MERGE + gt * 53;
#pragma unroll
        for (int i = 0; i < 50; i++) sims[i] += s[i];
        ss1_0 += s[50]; ss1_1 += s[51];
    }
    __syncthreads();

    // ---- epilogue: softmax + weighted partials (group 0 only) -------------
    float pA1 = 0.f, pA2 = 0.f, pP = 0.f, pS1 = 0.f, pS2 = 0.f;
    if (g == 0) {
        const float inv1_0 = 1.f / fmaxf(sqrtf(ss1_0), 1e-12f);
        const float inv1_1 = 1.f / fmaxf(sqrtf(ss1_1), 1e-12f);
        const float invT   = 1.f / 0.07f;  // SHIFT_TEMP + 1e-10 == 0.07f in fp32
#pragma unroll
        for (int j = 0; j < 2; j++) {
            float inv1 = j ? inv1_1 : inv1_0;
            float sn[25];
            float m = -1e30f;
#pragma unroll
            for (int dy = 0; dy < 5; dy++)
#pragma unroll
                for (int dx = 0; dx < 5; dx++) {
                    int t = (tr + dy) * HC + (wl + j + dx);
                    float v = sims[j * 25 + dy * 5 + dx] * inv1 * smem[SCR_SINV + t];
                    sn[dy * 5 + dx] = v;
                    m = fmaxf(m, v);
                }
            float se = 0.f, sv = 0.f;
#pragma unroll
            for (int s = 0; s < 25; s++) {
                float e = __expf((sn[s] - m) * invT);
                se += e; sv += e * sn[s];
            }
            float sb = sv / se;
            int tok = (th0 + tr) * WW + tw0 + wl + j;
            float wv1 = w1[b * NN + tok], wv2 = w2[b * NN + tok];
            pA1 += (1.f - sb) * wv1;
            pA2 += (1.f - sb) * wv2;
            pP  += sb;
            pS1 += wv1;
            pS2 += wv2;
        }
    }

    // ---- deterministic block reduction (5 values, 16 warps, no atomics) ---
#pragma unroll
    for (int o = 16; o > 0; o >>= 1) {
        pA1 += __shfl_down_sync(0xffffffffu, pA1, o);
        pA2 += __shfl_down_sync(0xffffffffu, pA2, o);
        pP  += __shfl_down_sync(0xffffffffu, pP,  o);
        pS1 += __shfl_down_sync(0xffffffffu, pS1, o);
        pS2 += __shfl_down_sync(0xffffffffu, pS2, o);
    }
    float* red = smem + SCR_RED;
    int wid = tid >> 5;
    if ((tid & 31) == 0) {
        red[wid] = pA1; red[16 + wid] = pA2; red[32 + wid] = pP;
        red[48 + wid] = pS1; red[64 + wid] = pS2;
    }
    __syncthreads();
    if (tid == 0) {
        float a1 = 0.f, a2 = 0.f, p = 0.f, s1 = 0.f, s2 = 0.f;
#pragma unroll
        for (int i = 0; i < 16; i++) {
            a1 += red[i]; a2 += red[16 + i]; p += red[32 + i];
            s1 += red[48 + i]; s2 += red[64 + i];
        }
        int bid = blockIdx.x + 3 * blockIdx.y + 18 * blockIdx.z;
        g_part[0][bid] = a1; g_part[1][bid] = a2; g_part[2][bid] = p;
        g_part[3][bid] = s1; g_part[4][bid] = s2;
    }
}

// ---------------------------------------------------------------------------
// Finalize: per-batch combine with deferred weight-normalization division
// ---------------------------------------------------------------------------
__global__ void finalize_kernel(float* __restrict__ out) {
    int tid = threadIdx.x;
    int w = tid >> 5, lane = tid & 31;     // warp w = batch w (w < 8)
    __shared__ float sh[16];
    float a1 = 0.f, a2 = 0.f, p = 0.f, s1 = 0.f, s2 = 0.f;
    if (w < BB && lane < 18) {             // 18 blocks per batch
        int bid = w * 18 + lane;
        a1 = g_part[0][bid]; a2 = g_part[1][bid]; p = g_part[2][bid];
        s1 = g_part[3][bid]; s2 = g_part[4][bid];
    }
#pragma unroll
    for (int o = 16; o > 0; o >>= 1) {
        a1 += __shfl_down_sync(0xffffffffu, a1, o);
        a2 += __shfl_down_sync(0xffffffffu, a2, o);
        p  += __shfl_down_sync(0xffffffffu, p,  o);
        s1 += __shfl_down_sync(0xffffffffu, s1, o);
        s2 += __shfl_down_sync(0xffffffffu, s2, o);
    }
    if (lane == 0 && w < BB) {
        sh[w]     = 0.5f * (a1 / (s1 + 1e-10f) + a2 / (s2 + 1e-10f)); // align_b
        sh[8 + w] = p;                                                 // pos sum
    }
    __syncthreads();
    if (tid == 0) {
        float ta = 0.f, tp = 0.f;
#pragma unroll
        for (int i = 0; i < BB; i++) { ta += sh[i]; tp += sh[8 + i]; }
        out[0] = ta / (float)BB;
        out[1] = tp / (float)(BB * NN);
    }
}

// ---------------------------------------------------------------------------
extern "C" void kernel_launch(void* const* d_in, const int* in_sizes, int n_in,
                              void* d_out, int out_size) {
    const float* z1 = (const float*)d_in[0];
    const float* z2 = (const float*)d_in[1];
    const float* w1 = (const float*)d_in[2];
    const float* w2 = (const float*)d_in[3];
    float* out = (float*)d_out;

    static int smem_set = 0;
    if (!smem_set) {
        cudaFuncSetAttribute(align_kernel,
                             cudaFuncAttributeMaxDynamicSharedMemorySize,
                             SMEM_FLT * sizeof(float));
        smem_set = 1;
    }
    dim3 grid(WW / TW, HH / TH, BB);       // (3, 6, 8) = 144 blocks
    align_kernel<<<grid, 512, SMEM_FLT * sizeof(float)>>>(z1, z2, w1, w2);
    finalize_kernel<<<1, 256>>>(out);
}